// round 1
// baseline (speedup 1.0000x reference)
#include <cuda_runtime.h>
#include <math.h>

// Problem constants
#define BB 2
#define SS 2048
#define TT 2048
#define DD 512
#define HH 8
#define DKK 64
#define FFN 2048
#define MM (BB*SS)          // 4096 rows for all row-major GEMMs
#define EPSV 1e-6f

// ---------------- Scratch (device globals; allocation-free) ----------------
__device__ float g_q   [MM*DD];
__device__ float g_k   [MM*DD];
__device__ float g_v   [MM*DD];
__device__ float g_tmp [MM*DD];
__device__ float g_out1[MM*DD];
__device__ float g_out2[MM*DD];
__device__ float g_ffn [MM*FFN];
__device__ float g_attn[(size_t)BB*HH*SS*SS];   // 268 MB probs scratch (used when aw not in d_out)

// ---------------- Generic GEMM: C = A[M,K] @ W[K,N] + bias, optional relu ----
// Tiles: 64x64x16, 256 threads, 4x4 per thread. M,N,K multiples of 64/16 here.
__global__ void gemm_bias_kernel(const float* __restrict__ A,
                                 const float* __restrict__ W,
                                 const float* __restrict__ bias,
                                 float* __restrict__ C,
                                 int M, int N, int K, int relu)
{
    __shared__ float sA[16][64];
    __shared__ float sB[16][65];

    int tid = threadIdx.x;
    int tr = tid >> 4;      // 0..15
    int tc = tid & 15;      // 0..15
    int rowBase = blockIdx.y * 64;
    int colBase = blockIdx.x * 64;

    float acc[4][4];
#pragma unroll
    for (int i = 0; i < 4; i++)
#pragma unroll
        for (int j = 0; j < 4; j++) acc[i][j] = 0.f;

    for (int k0 = 0; k0 < K; k0 += 16) {
        // load A tile 64x16 (1024 elems, 4/thread): consecutive tid -> consecutive kk
#pragma unroll
        for (int i = tid; i < 64*16; i += 256) {
            int m = i >> 4, kk = i & 15;
            sA[kk][m] = A[(size_t)(rowBase + m) * K + k0 + kk];
        }
        // load W tile 16x64: consecutive tid -> consecutive n (coalesced)
#pragma unroll
        for (int i = tid; i < 16*64; i += 256) {
            int kk = i >> 6, n = i & 63;
            sB[kk][n] = W[(size_t)(k0 + kk) * N + colBase + n];
        }
        __syncthreads();
#pragma unroll
        for (int kk = 0; kk < 16; kk++) {
            float a[4], b[4];
#pragma unroll
            for (int i = 0; i < 4; i++) a[i] = sA[kk][tr*4 + i];
#pragma unroll
            for (int j = 0; j < 4; j++) b[j] = sB[kk][tc*4 + j];
#pragma unroll
            for (int i = 0; i < 4; i++)
#pragma unroll
                for (int j = 0; j < 4; j++) acc[i][j] = fmaf(a[i], b[j], acc[i][j]);
        }
        __syncthreads();
    }

#pragma unroll
    for (int i = 0; i < 4; i++) {
        int r = rowBase + tr*4 + i;
#pragma unroll
        for (int j = 0; j < 4; j++) {
            int c = colBase + tc*4 + j;
            float v = acc[i][j] + bias[c];
            if (relu) v = fmaxf(v, 0.f);
            C[(size_t)r * N + c] = v;
        }
    }
}

// ---------------- QK^T logits (batched over B*H), fused scale + causal mask --
// Q,K stored as [B, L, D] row-major; head h occupies cols [h*64, h*64+64).
// L[bh, q, k] = (sum_d Q*K) * 0.125 + causal*(-1e9)
__global__ void qk_kernel(const float* __restrict__ Q,
                          const float* __restrict__ Kk,
                          float* __restrict__ L,
                          int causal)
{
    __shared__ float sQ[64][65];
    __shared__ float sK[64][65];

    int tid = threadIdx.x;
    int tr = tid >> 4;
    int tc = tid & 15;
    int bh = blockIdx.z;
    int b = bh >> 3, h = bh & 7;
    int q0 = blockIdx.y * 64;
    int c0 = blockIdx.x * 64;

    const float* qb = Q + (size_t)b*SS*DD + (size_t)h*DKK;
    const float* kb = Kk + (size_t)b*SS*DD + (size_t)h*DKK;
    float* lb = L + (size_t)bh*SS*SS;

    // full DK=64 fits in one tile -> single K-step
#pragma unroll
    for (int i = tid; i < 64*64; i += 256) {
        int m = i >> 6, d = i & 63;
        sQ[m][d] = qb[(size_t)(q0 + m) * DD + d];
        sK[m][d] = kb[(size_t)(c0 + m) * DD + d];
    }
    __syncthreads();

    float acc[4][4];
#pragma unroll
    for (int i = 0; i < 4; i++)
#pragma unroll
        for (int j = 0; j < 4; j++) acc[i][j] = 0.f;

#pragma unroll
    for (int d = 0; d < 64; d++) {
        float a[4], bv[4];
#pragma unroll
        for (int i = 0; i < 4; i++) a[i] = sQ[tr*4 + i][d];
#pragma unroll
        for (int j = 0; j < 4; j++) bv[j] = sK[tc*4 + j][d];
#pragma unroll
        for (int i = 0; i < 4; i++)
#pragma unroll
            for (int j = 0; j < 4; j++) acc[i][j] = fmaf(a[i], bv[j], acc[i][j]);
    }

#pragma unroll
    for (int i = 0; i < 4; i++) {
        int q = q0 + tr*4 + i;
#pragma unroll
        for (int j = 0; j < 4; j++) {
            int k = c0 + tc*4 + j;
            float v = acc[i][j] * 0.125f;   // 1/sqrt(64)
            if (causal && k > q) v += -1e9f;
            lb[(size_t)q * SS + k] = v;
        }
    }
}

// ---------------- Row softmax, in place. One block per row of 2048 ----------
__global__ void softmax_kernel(float* __restrict__ P)
{
    __shared__ float red[256];
    size_t row = blockIdx.x;
    float* p = P + row * (size_t)SS;
    int tid = threadIdx.x;

    float vals[8];
    float mx = -INFINITY;
#pragma unroll
    for (int i = 0; i < 8; i++) {
        vals[i] = p[tid + i*256];
        mx = fmaxf(mx, vals[i]);
    }
    red[tid] = mx; __syncthreads();
    for (int s = 128; s > 0; s >>= 1) {
        if (tid < s) red[tid] = fmaxf(red[tid], red[tid + s]);
        __syncthreads();
    }
    mx = red[0]; __syncthreads();

    float sum = 0.f;
#pragma unroll
    for (int i = 0; i < 8; i++) {
        vals[i] = expf(vals[i] - mx);
        sum += vals[i];
    }
    red[tid] = sum; __syncthreads();
    for (int s = 128; s > 0; s >>= 1) {
        if (tid < s) red[tid] += red[tid + s];
        __syncthreads();
    }
    float inv = 1.f / red[0];
#pragma unroll
    for (int i = 0; i < 8; i++) p[tid + i*256] = vals[i] * inv;
}

// ---------------- PV: out[b,q,h*64+n] = sum_k P[bh,q,k] * V[b,k,h*64+n] -----
// Batched GEMM per (b,h): M=2048, N=64, K=2048. Tiles 64x64x32.
__global__ void pv_kernel(const float* __restrict__ P,
                          const float* __restrict__ V,
                          float* __restrict__ O)
{
    __shared__ float sP[64][33];
    __shared__ float sV[32][65];

    int tid = threadIdx.x;
    int tr = tid >> 4;
    int tc = tid & 15;
    int bh = blockIdx.z;
    int b = bh >> 3, h = bh & 7;
    int q0 = blockIdx.y * 64;

    const float* pb = P + (size_t)bh*SS*SS;
    const float* vb = V + (size_t)b*SS*DD + (size_t)h*DKK;
    float* ob = O + (size_t)b*SS*DD + (size_t)h*DKK;

    float acc[4][4];
#pragma unroll
    for (int i = 0; i < 4; i++)
#pragma unroll
        for (int j = 0; j < 4; j++) acc[i][j] = 0.f;

    for (int k0 = 0; k0 < SS; k0 += 32) {
#pragma unroll
        for (int i = tid; i < 64*32; i += 256) {
            int m = i >> 5, kk = i & 31;
            sP[m][kk] = pb[(size_t)(q0 + m) * SS + k0 + kk];
        }
#pragma unroll
        for (int i = tid; i < 32*64; i += 256) {
            int kk = i >> 6, n = i & 63;
            sV[kk][n] = vb[(size_t)(k0 + kk) * DD + n];
        }
        __syncthreads();
#pragma unroll
        for (int kk = 0; kk < 32; kk++) {
            float a[4], bv[4];
#pragma unroll
            for (int i = 0; i < 4; i++) a[i] = sP[tr*4 + i][kk];
#pragma unroll
            for (int j = 0; j < 4; j++) bv[j] = sV[kk][tc*4 + j];
#pragma unroll
            for (int i = 0; i < 4; i++)
#pragma unroll
                for (int j = 0; j < 4; j++) acc[i][j] = fmaf(a[i], bv[j], acc[i][j]);
        }
        __syncthreads();
    }

#pragma unroll
    for (int i = 0; i < 4; i++) {
        int q = q0 + tr*4 + i;
#pragma unroll
        for (int j = 0; j < 4; j++) {
            ob[(size_t)q * DD + tc*4 + j] = acc[i][j];
        }
    }
}

// ---------------- residual add + LayerNorm over D=512 -----------------------
__global__ void add_ln_kernel(const float* __restrict__ a,
                              const float* __restrict__ res,
                              const float* __restrict__ g,
                              const float* __restrict__ be,
                              float* __restrict__ out)
{
    __shared__ float red[128];
    size_t row = blockIdx.x;
    const float* ar = a + row * DD;
    const float* rr = res + row * DD;
    float* orow = out + row * DD;
    int tid = threadIdx.x;

    float vals[4];
    float s = 0.f;
#pragma unroll
    for (int i = 0; i < 4; i++) {
        vals[i] = ar[tid + i*128] + rr[tid + i*128];
        s += vals[i];
    }
    red[tid] = s; __syncthreads();
    for (int st = 64; st > 0; st >>= 1) {
        if (tid < st) red[tid] += red[tid + st];
        __syncthreads();
    }
    float mean = red[0] * (1.f / DD); __syncthreads();

    float sq = 0.f;
#pragma unroll
    for (int i = 0; i < 4; i++) {
        float d = vals[i] - mean;
        sq += d * d;
    }
    red[tid] = sq; __syncthreads();
    for (int st = 64; st > 0; st >>= 1) {
        if (tid < st) red[tid] += red[tid + st];
        __syncthreads();
    }
    float inv = rsqrtf(red[0] * (1.f / DD) + EPSV);
#pragma unroll
    for (int i = 0; i < 4; i++) {
        int c = tid + i*128;
        orow[c] = (vals[i] - mean) * inv * g[c] + be[c];
    }
}

// ---------------- launch helpers ----------------
static inline void gemm(const float* A, const float* W, const float* bias,
                        float* C, int M, int N, int K, int relu)
{
    dim3 grid(N / 64, M / 64);
    gemm_bias_kernel<<<grid, 256>>>(A, W, bias, C, M, N, K, relu);
}

extern "C" void kernel_launch(void* const* d_in, const int* in_sizes, int n_in,
                              void* d_out, int out_size)
{
    const float* x    = (const float*)d_in[0];
    const float* enc  = (const float*)d_in[1];
    // d_in[2] = look_ahead_mask (causal; applied analytically)
    const float* wq1 = (const float*)d_in[3];  const float* bq1 = (const float*)d_in[4];
    const float* wk1 = (const float*)d_in[5];  const float* bk1 = (const float*)d_in[6];
    const float* wv1 = (const float*)d_in[7];  const float* bv1 = (const float*)d_in[8];
    const float* wo1 = (const float*)d_in[9];  const float* bo1 = (const float*)d_in[10];
    const float* wq2 = (const float*)d_in[11]; const float* bq2 = (const float*)d_in[12];
    const float* wk2 = (const float*)d_in[13]; const float* bk2 = (const float*)d_in[14];
    const float* wv2 = (const float*)d_in[15]; const float* bv2 = (const float*)d_in[16];
    const float* wo2 = (const float*)d_in[17]; const float* bo2 = (const float*)d_in[18];
    const float* wf1 = (const float*)d_in[19]; const float* bf1 = (const float*)d_in[20];
    const float* wf2 = (const float*)d_in[21]; const float* bf2 = (const float*)d_in[22];
    const float* g1  = (const float*)d_in[23]; const float* be1 = (const float*)d_in[24];
    const float* g2  = (const float*)d_in[25]; const float* be2 = (const float*)d_in[26];
    const float* g3  = (const float*)d_in[27]; const float* be3 = (const float*)d_in[28];

    float* out3 = (float*)d_out;

    // device scratch pointers
    float *q, *k, *v, *tmp, *o1, *o2, *ffn, *attn;
    cudaGetSymbolAddress((void**)&q,    g_q);
    cudaGetSymbolAddress((void**)&k,    g_k);
    cudaGetSymbolAddress((void**)&v,    g_v);
    cudaGetSymbolAddress((void**)&tmp,  g_tmp);
    cudaGetSymbolAddress((void**)&o1,   g_out1);
    cudaGetSymbolAddress((void**)&o2,   g_out2);
    cudaGetSymbolAddress((void**)&ffn,  g_ffn);
    cudaGetSymbolAddress((void**)&attn, g_attn);

    const size_t OUT3 = (size_t)BB*SS*DD;                 // 2,097,152
    const size_t AW   = (size_t)BB*HH*SS*SS;              // 67,108,864
    float* p1;
    float* p2;
    if ((size_t)out_size >= OUT3 + 2*AW) {
        p1 = out3 + OUT3;       // aw1 region
        p2 = out3 + OUT3 + AW;  // aw2 region
    } else {
        p1 = attn;              // scratch, reused sequentially
        p2 = attn;
    }

    dim3 qkGrid(SS/64, SS/64, BB*HH);
    dim3 pvGrid(1, SS/64, BB*HH);
    int nRows = BB*HH*SS;   // softmax rows
    int nLn   = BB*SS;      // layernorm rows

    // ================= MHA1 (causal self-attention) =================
    gemm(x, wq1, bq1, q, MM, DD, DD, 0);
    gemm(x, wk1, bk1, k, MM, DD, DD, 0);
    gemm(x, wv1, bv1, v, MM, DD, DD, 0);
    qk_kernel<<<qkGrid, 256>>>(q, k, p1, 1);
    softmax_kernel<<<nRows, 256>>>(p1);
    pv_kernel<<<pvGrid, 256>>>(p1, v, tmp);
    gemm(tmp, wo1, bo1, q, MM, DD, DD, 0);          // attn1 -> q (reuse)
    add_ln_kernel<<<nLn, 128>>>(q, x, g1, be1, o1);

    // ================= MHA2 (cross-attention, no mask) ==============
    gemm(o1, wq2, bq2, q, MM, DD, DD, 0);
    gemm(enc, wk2, bk2, k, MM, DD, DD, 0);
    gemm(enc, wv2, bv2, v, MM, DD, DD, 0);
    qk_kernel<<<qkGrid, 256>>>(q, k, p2, 0);
    softmax_kernel<<<nRows, 256>>>(p2);
    pv_kernel<<<pvGrid, 256>>>(p2, v, tmp);
    gemm(tmp, wo2, bo2, q, MM, DD, DD, 0);
    add_ln_kernel<<<nLn, 128>>>(q, o1, g2, be2, o2);

    // ================= FFN =================
    gemm(o2, wf1, bf1, ffn, MM, FFN, DD, 1);        // relu fused
    gemm(ffn, wf2, bf2, q, MM, DD, FFN, 0);
    add_ln_kernel<<<nLn, 128>>>(q, o2, g3, be3, out3);
}

// round 2
// speedup vs baseline: 2.1142x; 2.1142x over previous
#include <cuda_runtime.h>
#include <math.h>

#define BB 2
#define SS 2048
#define DD 512
#define HH 8
#define DKK 64
#define FFN 2048
#define MM (BB*SS)
#define EPSV 1e-6f

// ---------------- Scratch (device globals; allocation-free) ----------------
__device__ float g_q   [MM*DD];
__device__ float g_k   [MM*DD];
__device__ float g_v   [MM*DD];
__device__ float g_tmp [MM*DD];
__device__ float g_out1[MM*DD];
__device__ float g_out2[MM*DD];
__device__ float g_ffn [MM*FFN];
__device__ float g_attn[(size_t)BB*HH*SS*SS];

// ---------------- GEMM v2: C = A[M,K] @ W[K,N] + bias, optional relu --------
// 128x64 block tile, 256 threads, 8x4 per thread, K-step 16, float4 everywhere.
__global__ __launch_bounds__(256) void gemm_bias_kernel(
    const float* __restrict__ A, const float* __restrict__ W,
    const float* __restrict__ bias, float* __restrict__ C,
    int M, int N, int K, int relu)
{
    __shared__ float sA[16][128];   // transposed: sA[kk][m]
    __shared__ float sB[16][64];

    int tid = threadIdx.x;
    int tr = tid >> 4;      // 0..15 -> rows tr*8..tr*8+7
    int tc = tid & 15;      // 0..15 -> cols tc*4..tc*4+3
    int rowBase = blockIdx.y * 128;
    int colBase = blockIdx.x * 64;

    float acc[8][4];
#pragma unroll
    for (int i = 0; i < 8; i++)
#pragma unroll
        for (int j = 0; j < 4; j++) acc[i][j] = 0.f;

    for (int k0 = 0; k0 < K; k0 += 16) {
        // A tile: 128x16 = 512 float4, 2 per thread (coalesced), store transposed
#pragma unroll
        for (int t = 0; t < 2; t++) {
            int idx = tid + t * 256;
            int m = idx >> 2;
            int kq = (idx & 3) * 4;
            float4 av = *reinterpret_cast<const float4*>(
                &A[(size_t)(rowBase + m) * K + k0 + kq]);
            sA[kq + 0][m] = av.x;
            sA[kq + 1][m] = av.y;
            sA[kq + 2][m] = av.z;
            sA[kq + 3][m] = av.w;
        }
        // W tile: 16x64 = 256 float4, 1 per thread (coalesced)
        {
            int kk = tid >> 4;
            int nq = (tid & 15) * 4;
            *reinterpret_cast<float4*>(&sB[kk][nq]) =
                *reinterpret_cast<const float4*>(&W[(size_t)(k0 + kk) * N + colBase + nq]);
        }
        __syncthreads();

#pragma unroll
        for (int kk = 0; kk < 16; kk++) {
            float a[8], b[4];
            *reinterpret_cast<float4*>(&a[0]) = *reinterpret_cast<float4*>(&sA[kk][tr * 8]);
            *reinterpret_cast<float4*>(&a[4]) = *reinterpret_cast<float4*>(&sA[kk][tr * 8 + 4]);
            *reinterpret_cast<float4*>(&b[0]) = *reinterpret_cast<float4*>(&sB[kk][tc * 4]);
#pragma unroll
            for (int i = 0; i < 8; i++)
#pragma unroll
                for (int j = 0; j < 4; j++) acc[i][j] = fmaf(a[i], b[j], acc[i][j]);
        }
        __syncthreads();
    }

    float4 bv = *reinterpret_cast<const float4*>(&bias[colBase + tc * 4]);
#pragma unroll
    for (int i = 0; i < 8; i++) {
        int r = rowBase + tr * 8 + i;
        float4 o;
        o.x = acc[i][0] + bv.x;
        o.y = acc[i][1] + bv.y;
        o.z = acc[i][2] + bv.z;
        o.w = acc[i][3] + bv.w;
        if (relu) {
            o.x = fmaxf(o.x, 0.f); o.y = fmaxf(o.y, 0.f);
            o.z = fmaxf(o.z, 0.f); o.w = fmaxf(o.w, 0.f);
        }
        *reinterpret_cast<float4*>(&C[(size_t)r * N + colBase + tc * 4]) = o;
    }
}

// ---------------- QK^T logits (batched B*H), fused scale + causal mask ------
__global__ __launch_bounds__(256) void qk_kernel(
    const float* __restrict__ Q, const float* __restrict__ Kk,
    float* __restrict__ L, int causal)
{
    int tid = threadIdx.x;
    int tr = tid >> 4;
    int tc = tid & 15;
    int bh = blockIdx.z;
    int b = bh >> 3, h = bh & 7;
    int q0 = blockIdx.y * 64;
    int c0 = blockIdx.x * 64;

    float* lb = L + (size_t)bh * SS * SS;

    // fully-masked tile: write -1e9 and exit (softmax turns it into 0)
    if (causal && c0 > q0 + 63) {
        float4 neg = make_float4(-1e9f, -1e9f, -1e9f, -1e9f);
#pragma unroll
        for (int i = 0; i < 4; i++) {
            int q = q0 + tr * 4 + i;
            *reinterpret_cast<float4*>(&lb[(size_t)q * SS + c0 + tc * 4]) = neg;
        }
        return;
    }

    __shared__ float sQ[64][65];
    __shared__ float sK[64][65];

    const float* qb = Q + (size_t)b * SS * DD + (size_t)h * DKK;
    const float* kb = Kk + (size_t)b * SS * DD + (size_t)h * DKK;

#pragma unroll
    for (int i = tid; i < 64 * 64; i += 256) {
        int m = i >> 6, d = i & 63;
        sQ[m][d] = qb[(size_t)(q0 + m) * DD + d];
        sK[m][d] = kb[(size_t)(c0 + m) * DD + d];
    }
    __syncthreads();

    float acc[4][4];
#pragma unroll
    for (int i = 0; i < 4; i++)
#pragma unroll
        for (int j = 0; j < 4; j++) acc[i][j] = 0.f;

#pragma unroll
    for (int d = 0; d < 64; d++) {
        float a[4], bvv[4];
#pragma unroll
        for (int i = 0; i < 4; i++) a[i] = sQ[tr * 4 + i][d];
#pragma unroll
        for (int j = 0; j < 4; j++) bvv[j] = sK[tc * 4 + j][d];
#pragma unroll
        for (int i = 0; i < 4; i++)
#pragma unroll
            for (int j = 0; j < 4; j++) acc[i][j] = fmaf(a[i], bvv[j], acc[i][j]);
    }

#pragma unroll
    for (int i = 0; i < 4; i++) {
        int q = q0 + tr * 4 + i;
        float4 o;
        float v0 = acc[i][0] * 0.125f, v1 = acc[i][1] * 0.125f;
        float v2 = acc[i][2] * 0.125f, v3 = acc[i][3] * 0.125f;
        int k = c0 + tc * 4;
        if (causal) {
            if (k + 0 > q) v0 += -1e9f;
            if (k + 1 > q) v1 += -1e9f;
            if (k + 2 > q) v2 += -1e9f;
            if (k + 3 > q) v3 += -1e9f;
        }
        o.x = v0; o.y = v1; o.z = v2; o.w = v3;
        *reinterpret_cast<float4*>(&lb[(size_t)q * SS + k]) = o;
    }
}

// ---------------- Row softmax, in place, float4 + __expf --------------------
__global__ __launch_bounds__(256) void softmax_kernel(float* __restrict__ P)
{
    __shared__ float red[256];
    size_t row = blockIdx.x;
    float* p = P + row * (size_t)SS;
    int tid = threadIdx.x;

    float4 v0 = *reinterpret_cast<float4*>(&p[tid * 4]);
    float4 v1 = *reinterpret_cast<float4*>(&p[1024 + tid * 4]);

    float mx = fmaxf(fmaxf(fmaxf(v0.x, v0.y), fmaxf(v0.z, v0.w)),
                     fmaxf(fmaxf(v1.x, v1.y), fmaxf(v1.z, v1.w)));
    red[tid] = mx; __syncthreads();
    for (int s = 128; s > 0; s >>= 1) {
        if (tid < s) red[tid] = fmaxf(red[tid], red[tid + s]);
        __syncthreads();
    }
    mx = red[0]; __syncthreads();

    v0.x = __expf(v0.x - mx); v0.y = __expf(v0.y - mx);
    v0.z = __expf(v0.z - mx); v0.w = __expf(v0.w - mx);
    v1.x = __expf(v1.x - mx); v1.y = __expf(v1.y - mx);
    v1.z = __expf(v1.z - mx); v1.w = __expf(v1.w - mx);

    float sum = v0.x + v0.y + v0.z + v0.w + v1.x + v1.y + v1.z + v1.w;
    red[tid] = sum; __syncthreads();
    for (int s = 128; s > 0; s >>= 1) {
        if (tid < s) red[tid] += red[tid + s];
        __syncthreads();
    }
    float inv = 1.f / red[0];

    v0.x *= inv; v0.y *= inv; v0.z *= inv; v0.w *= inv;
    v1.x *= inv; v1.y *= inv; v1.z *= inv; v1.w *= inv;
    *reinterpret_cast<float4*>(&p[tid * 4]) = v0;
    *reinterpret_cast<float4*>(&p[1024 + tid * 4]) = v1;
}

// ---------------- PV v2: 128x64 tile, 8x4 per thread ------------------------
__global__ __launch_bounds__(256) void pv_kernel(
    const float* __restrict__ P, const float* __restrict__ V,
    float* __restrict__ O)
{
    __shared__ float sP[16][128];   // transposed: sP[kk][m]
    __shared__ float sV[16][64];

    int tid = threadIdx.x;
    int tr = tid >> 4;
    int tc = tid & 15;
    int bh = blockIdx.z;
    int b = bh >> 3, h = bh & 7;
    int q0 = blockIdx.y * 128;

    const float* pb = P + (size_t)bh * SS * SS;
    const float* vb = V + (size_t)b * SS * DD + (size_t)h * DKK;
    float* ob = O + (size_t)b * SS * DD + (size_t)h * DKK;

    float acc[8][4];
#pragma unroll
    for (int i = 0; i < 8; i++)
#pragma unroll
        for (int j = 0; j < 4; j++) acc[i][j] = 0.f;

    for (int k0 = 0; k0 < SS; k0 += 16) {
#pragma unroll
        for (int t = 0; t < 2; t++) {
            int idx = tid + t * 256;
            int m = idx >> 2;
            int kq = (idx & 3) * 4;
            float4 av = *reinterpret_cast<const float4*>(
                &pb[(size_t)(q0 + m) * SS + k0 + kq]);
            sP[kq + 0][m] = av.x;
            sP[kq + 1][m] = av.y;
            sP[kq + 2][m] = av.z;
            sP[kq + 3][m] = av.w;
        }
        {
            int kk = tid >> 4;
            int nq = (tid & 15) * 4;
            *reinterpret_cast<float4*>(&sV[kk][nq]) =
                *reinterpret_cast<const float4*>(&vb[(size_t)(k0 + kk) * DD + nq]);
        }
        __syncthreads();

#pragma unroll
        for (int kk = 0; kk < 16; kk++) {
            float a[8], bvv[4];
            *reinterpret_cast<float4*>(&a[0]) = *reinterpret_cast<float4*>(&sP[kk][tr * 8]);
            *reinterpret_cast<float4*>(&a[4]) = *reinterpret_cast<float4*>(&sP[kk][tr * 8 + 4]);
            *reinterpret_cast<float4*>(&bvv[0]) = *reinterpret_cast<float4*>(&sV[kk][tc * 4]);
#pragma unroll
            for (int i = 0; i < 8; i++)
#pragma unroll
                for (int j = 0; j < 4; j++) acc[i][j] = fmaf(a[i], bvv[j], acc[i][j]);
        }
        __syncthreads();
    }

#pragma unroll
    for (int i = 0; i < 8; i++) {
        int q = q0 + tr * 8 + i;
        float4 o;
        o.x = acc[i][0]; o.y = acc[i][1]; o.z = acc[i][2]; o.w = acc[i][3];
        *reinterpret_cast<float4*>(&ob[(size_t)q * DD + tc * 4]) = o;
    }
}

// ---------------- residual add + LayerNorm over D=512, float4 ---------------
__global__ __launch_bounds__(128) void add_ln_kernel(
    const float* __restrict__ a, const float* __restrict__ res,
    const float* __restrict__ g, const float* __restrict__ be,
    float* __restrict__ out)
{
    __shared__ float red[128];
    size_t row = blockIdx.x;
    int tid = threadIdx.x;

    float4 va = *reinterpret_cast<const float4*>(&a[row * DD + tid * 4]);
    float4 vr = *reinterpret_cast<const float4*>(&res[row * DD + tid * 4]);
    float4 v;
    v.x = va.x + vr.x; v.y = va.y + vr.y; v.z = va.z + vr.z; v.w = va.w + vr.w;

    float s = v.x + v.y + v.z + v.w;
    red[tid] = s; __syncthreads();
    for (int st = 64; st > 0; st >>= 1) {
        if (tid < st) red[tid] += red[tid + st];
        __syncthreads();
    }
    float mean = red[0] * (1.f / DD); __syncthreads();

    float dx = v.x - mean, dy = v.y - mean, dz = v.z - mean, dw = v.w - mean;
    float sq = dx * dx + dy * dy + dz * dz + dw * dw;
    red[tid] = sq; __syncthreads();
    for (int st = 64; st > 0; st >>= 1) {
        if (tid < st) red[tid] += red[tid + st];
        __syncthreads();
    }
    float inv = rsqrtf(red[0] * (1.f / DD) + EPSV);

    float4 gg = *reinterpret_cast<const float4*>(&g[tid * 4]);
    float4 bb = *reinterpret_cast<const float4*>(&be[tid * 4]);
    float4 o;
    o.x = dx * inv * gg.x + bb.x;
    o.y = dy * inv * gg.y + bb.y;
    o.z = dz * inv * gg.z + bb.z;
    o.w = dw * inv * gg.w + bb.w;
    *reinterpret_cast<float4*>(&out[row * DD + tid * 4]) = o;
}

// ---------------- launch helpers ----------------
static inline void gemm(const float* A, const float* W, const float* bias,
                        float* C, int M, int N, int K, int relu)
{
    dim3 grid(N / 64, M / 128);
    gemm_bias_kernel<<<grid, 256>>>(A, W, bias, C, M, N, K, relu);
}

extern "C" void kernel_launch(void* const* d_in, const int* in_sizes, int n_in,
                              void* d_out, int out_size)
{
    const float* x    = (const float*)d_in[0];
    const float* enc  = (const float*)d_in[1];
    const float* wq1 = (const float*)d_in[3];  const float* bq1 = (const float*)d_in[4];
    const float* wk1 = (const float*)d_in[5];  const float* bk1 = (const float*)d_in[6];
    const float* wv1 = (const float*)d_in[7];  const float* bv1 = (const float*)d_in[8];
    const float* wo1 = (const float*)d_in[9];  const float* bo1 = (const float*)d_in[10];
    const float* wq2 = (const float*)d_in[11]; const float* bq2 = (const float*)d_in[12];
    const float* wk2 = (const float*)d_in[13]; const float* bk2 = (const float*)d_in[14];
    const float* wv2 = (const float*)d_in[15]; const float* bv2 = (const float*)d_in[16];
    const float* wo2 = (const float*)d_in[17]; const float* bo2 = (const float*)d_in[18];
    const float* wf1 = (const float*)d_in[19]; const float* bf1 = (const float*)d_in[20];
    const float* wf2 = (const float*)d_in[21]; const float* bf2 = (const float*)d_in[22];
    const float* g1  = (const float*)d_in[23]; const float* be1 = (const float*)d_in[24];
    const float* g2  = (const float*)d_in[25]; const float* be2 = (const float*)d_in[26];
    const float* g3  = (const float*)d_in[27]; const float* be3 = (const float*)d_in[28];

    float* out3 = (float*)d_out;

    float *q, *k, *v, *tmp, *o1, *o2, *ffn, *attn;
    cudaGetSymbolAddress((void**)&q,    g_q);
    cudaGetSymbolAddress((void**)&k,    g_k);
    cudaGetSymbolAddress((void**)&v,    g_v);
    cudaGetSymbolAddress((void**)&tmp,  g_tmp);
    cudaGetSymbolAddress((void**)&o1,   g_out1);
    cudaGetSymbolAddress((void**)&o2,   g_out2);
    cudaGetSymbolAddress((void**)&ffn,  g_ffn);
    cudaGetSymbolAddress((void**)&attn, g_attn);

    const size_t OUT3 = (size_t)BB * SS * DD;
    const size_t AW   = (size_t)BB * HH * SS * SS;
    float* p1;
    float* p2;
    if ((size_t)out_size >= OUT3 + 2 * AW) {
        p1 = out3 + OUT3;
        p2 = out3 + OUT3 + AW;
    } else {
        p1 = attn;
        p2 = attn;
    }

    dim3 qkGrid(SS / 64, SS / 64, BB * HH);
    dim3 pvGrid(1, SS / 128, BB * HH);
    int nRows = BB * HH * SS;
    int nLn   = BB * SS;

    // ================= MHA1 (causal self-attention) =================
    gemm(x, wq1, bq1, q, MM, DD, DD, 0);
    gemm(x, wk1, bk1, k, MM, DD, DD, 0);
    gemm(x, wv1, bv1, v, MM, DD, DD, 0);
    qk_kernel<<<qkGrid, 256>>>(q, k, p1, 1);
    softmax_kernel<<<nRows, 256>>>(p1);
    pv_kernel<<<pvGrid, 256>>>(p1, v, tmp);
    gemm(tmp, wo1, bo1, q, MM, DD, DD, 0);
    add_ln_kernel<<<nLn, 128>>>(q, x, g1, be1, o1);

    // ================= MHA2 (cross-attention, no mask) ==============
    gemm(o1, wq2, bq2, q, MM, DD, DD, 0);
    gemm(enc, wk2, bk2, k, MM, DD, DD, 0);
    gemm(enc, wv2, bv2, v, MM, DD, DD, 0);
    qk_kernel<<<qkGrid, 256>>>(q, k, p2, 0);
    softmax_kernel<<<nRows, 256>>>(p2);
    pv_kernel<<<pvGrid, 256>>>(p2, v, tmp);
    gemm(tmp, wo2, bo2, q, MM, DD, DD, 0);
    add_ln_kernel<<<nLn, 128>>>(q, o1, g2, be2, o2);

    // ================= FFN =================
    gemm(o2, wf1, bf1, ffn, MM, FFN, DD, 1);
    gemm(ffn, wf2, bf2, q, MM, DD, FFN, 0);
    add_ln_kernel<<<nLn, 128>>>(q, o2, g3, be3, out3);
}

// round 5
// speedup vs baseline: 3.0377x; 1.4368x over previous
#include <cuda_runtime.h>
#include <cuda_bf16.h>
#include <math.h>
#include <stdint.h>

#define BB 2
#define SS 2048
#define DD 512
#define HH 8
#define DKK 64
#define FFN 2048
#define MM (BB*SS)
#define EPSV 1e-6f

// ================= scratch (device globals; allocation-free) ================
__device__ float g_q   [MM*DD];
__device__ float g_k   [MM*DD];
__device__ float g_v   [MM*DD];
__device__ float g_tmp [MM*DD];
__device__ float g_out1[MM*DD];
__device__ float g_out2[MM*DD];
__device__ float g_ffn [MM*FFN];
__device__ float g_attn[(size_t)BB*HH*SS*SS];
// bf16 split buffers
__device__ __nv_bfloat16 g_ah[(size_t)MM*FFN];
__device__ __nv_bfloat16 g_al[(size_t)MM*FFN];
__device__ __nv_bfloat16 g_bh[(size_t)MM*DD];
__device__ __nv_bfloat16 g_bl[(size_t)MM*DD];
__device__ __nv_bfloat16 g_wh[(size_t)FFN*DD];
__device__ __nv_bfloat16 g_wl[(size_t)FFN*DD];

// ================= low-level helpers (sm_80-compatible PTX only) ============
__device__ __forceinline__ uint32_t smem_u32(const void* p) {
    uint32_t a;
    asm("{ .reg .u64 t; cvta.to.shared.u64 t, %1; cvt.u32.u64 %0, t; }" : "=r"(a) : "l"(p));
    return a;
}
__device__ __forceinline__ void cp16(uint32_t dst, const void* src) {
    asm volatile("cp.async.cg.shared.global [%0], [%1], 16;" :: "r"(dst), "l"(src));
}
#define CP_COMMIT() asm volatile("cp.async.commit_group;" ::: "memory")
#define CP_WAIT1()  asm volatile("cp.async.wait_group 1;" ::: "memory")

__device__ __forceinline__ void ldsm4(uint32_t& r0, uint32_t& r1, uint32_t& r2,
                                      uint32_t& r3, uint32_t addr) {
    asm volatile("ldmatrix.sync.aligned.m8n8.x4.shared.b16 {%0,%1,%2,%3}, [%4];"
                 : "=r"(r0), "=r"(r1), "=r"(r2), "=r"(r3) : "r"(addr));
}
__device__ __forceinline__ void ldsm4t(uint32_t& r0, uint32_t& r1, uint32_t& r2,
                                       uint32_t& r3, uint32_t addr) {
    asm volatile("ldmatrix.sync.aligned.m8n8.x4.trans.shared.b16 {%0,%1,%2,%3}, [%4];"
                 : "=r"(r0), "=r"(r1), "=r"(r2), "=r"(r3) : "r"(addr));
}
__device__ __forceinline__ void mma16816(float* c, const uint32_t* a, const uint32_t* b) {
    asm volatile(
        "mma.sync.aligned.m16n8k16.row.col.f32.bf16.bf16.f32 "
        "{%0,%1,%2,%3}, {%4,%5,%6,%7}, {%8,%9}, {%0,%1,%2,%3};"
        : "+f"(c[0]), "+f"(c[1]), "+f"(c[2]), "+f"(c[3])
        : "r"(a[0]), "r"(a[1]), "r"(a[2]), "r"(a[3]), "r"(b[0]), "r"(b[1]));
}

// ============== HMMA GEMM: C = A[M,K] @ W[K,N] + bias (bf16x3, fp32 acc) ====
// A split (Ah,Al) row-major [M,K]; W split (Bh,Bl) native [K,N].
// CTA 128x128, 8 warps (2x4), warp tile 64x32, K-chunk 64, 2-stage cp.async.
#define STAGE_BYTES 65536
#define SM_TOTAL    (2*STAGE_BYTES)
// per-stage offsets: Ah 0..16K, Al 16K..32K, Bh 32K..48K (two 8K subtiles n0-63 / n64-127), Bl 48K..64K

__global__ __launch_bounds__(256) void mma_gemm_kernel(
    const __nv_bfloat16* __restrict__ Ah, const __nv_bfloat16* __restrict__ Al,
    const __nv_bfloat16* __restrict__ Bh, const __nv_bfloat16* __restrict__ Bl,
    const float* __restrict__ bias, float* __restrict__ C,
    int M, int N, int K, int relu)
{
    extern __shared__ char smem[];
    const int tid = threadIdx.x;
    const int lane = tid & 31;
    const int wid = tid >> 5;
    const int warp_m = wid & 1;        // 0..1 -> m offset 0/64
    const int warp_n = wid >> 1;       // 0..3 -> n offset 0/32/64/96
    const int rowBase = blockIdx.y * 128;
    const int colBase = blockIdx.x * 128;
    const uint32_t sbase = smem_u32(smem);

    float acc[4][4][4];
#pragma unroll
    for (int i = 0; i < 4; i++)
#pragma unroll
        for (int j = 0; j < 4; j++)
#pragma unroll
            for (int t = 0; t < 4; t++) acc[i][j][t] = 0.f;

    const int nChunks = K >> 6;

    // ---- stage loader ----
    auto load_stage = [&](int kc, int s) {
        uint32_t st = sbase + s * STAGE_BYTES;
        int k0 = kc * 64;
        // A hi/lo: 128 rows x 64 bf16 (128B rows), 1024 16B-chunks each
#pragma unroll
        for (int i = 0; i < 4; i++) {
            int id = tid + i * 256;
            int r = id >> 3, c16 = id & 7;
            uint32_t off = (uint32_t)(r * 128 + c16 * 16);
            off ^= (off >> 3) & 0x70;
            size_t g = (size_t)(rowBase + r) * K + k0 + c16 * 8;
            cp16(st + off,         Ah + g);
            cp16(st + 16384 + off, Al + g);
        }
        // B hi/lo: 64 k-rows x 128 n; two subtiles of [64][64] (128B rows)
#pragma unroll
        for (int i = 0; i < 4; i++) {
            int id = tid + i * 256;
            int kk = id >> 4, nc = id & 15;
            int j = nc >> 3, cc = nc & 7;
            uint32_t off = (uint32_t)(kk * 128 + cc * 16);
            off ^= (off >> 3) & 0x70;
            off += (uint32_t)(j * 8192);
            size_t g = (size_t)(k0 + kk) * N + colBase + nc * 8;
            cp16(st + 32768 + off, Bh + g);
            cp16(st + 49152 + off, Bl + g);
        }
    };

    load_stage(0, 0);
    CP_COMMIT();

    const int bsub = warp_n >> 1;             // B subtile index
    const int nb2  = (warp_n & 1) * 64;       // byte offset of n within subtile

    for (int c = 0; c < nChunks; c++) {
        if (c + 1 < nChunks) load_stage(c + 1, (c + 1) & 1);
        CP_COMMIT();
        CP_WAIT1();
        __syncthreads();

        uint32_t st = sbase + (c & 1) * STAGE_BYTES;
#pragma unroll
        for (int k16 = 0; k16 < 4; k16++) {
            uint32_t ahf[4][4], alf[4][4], bhf[2][4], blf[2][4];
#pragma unroll
            for (int mt = 0; mt < 4; mt++) {
                int row = warp_m * 64 + mt * 16 + (lane & 15);
                uint32_t off = (uint32_t)(row * 128 + k16 * 32 + (lane >> 4) * 16);
                off ^= (off >> 3) & 0x70;
                ldsm4(ahf[mt][0], ahf[mt][1], ahf[mt][2], ahf[mt][3], st + off);
                ldsm4(alf[mt][0], alf[mt][1], alf[mt][2], alf[mt][3], st + 16384 + off);
            }
#pragma unroll
            for (int nt = 0; nt < 2; nt++) {
                int kk = k16 * 16 + (lane & 15);
                uint32_t off = (uint32_t)(kk * 128 + nb2 + nt * 32 + (lane >> 4) * 16);
                off ^= (off >> 3) & 0x70;
                off += (uint32_t)(bsub * 8192);
                ldsm4t(bhf[nt][0], bhf[nt][1], bhf[nt][2], bhf[nt][3], st + 32768 + off);
                ldsm4t(blf[nt][0], blf[nt][1], blf[nt][2], blf[nt][3], st + 49152 + off);
            }
#pragma unroll
            for (int mt = 0; mt < 4; mt++) {
#pragma unroll
                for (int n8 = 0; n8 < 4; n8++) {
                    const uint32_t* bh = &bhf[n8 >> 1][(n8 & 1) * 2];
                    const uint32_t* bl = &blf[n8 >> 1][(n8 & 1) * 2];
                    mma16816(acc[mt][n8], ahf[mt], bh);
                    mma16816(acc[mt][n8], alf[mt], bh);
                    mma16816(acc[mt][n8], ahf[mt], bl);
                }
            }
        }
        __syncthreads();
    }

    // ---- epilogue: bias + optional relu, fp32 out ----
#pragma unroll
    for (int mt = 0; mt < 4; mt++) {
        int r0 = rowBase + warp_m * 64 + mt * 16 + (lane >> 2);
#pragma unroll
        for (int n8 = 0; n8 < 4; n8++) {
            int col = colBase + warp_n * 32 + n8 * 8 + (lane & 3) * 2;
            float bx = bias[col], by = bias[col + 1];
            float2 v0, v1;
            v0.x = acc[mt][n8][0] + bx; v0.y = acc[mt][n8][1] + by;
            v1.x = acc[mt][n8][2] + bx; v1.y = acc[mt][n8][3] + by;
            if (relu) {
                v0.x = fmaxf(v0.x, 0.f); v0.y = fmaxf(v0.y, 0.f);
                v1.x = fmaxf(v1.x, 0.f); v1.y = fmaxf(v1.y, 0.f);
            }
            *(float2*)&C[(size_t)r0 * N + col] = v0;
            *(float2*)&C[(size_t)(r0 + 8) * N + col] = v1;
        }
    }
}

// ================= fp32 -> (hi, lo) bf16 split, elementwise =================
__global__ __launch_bounds__(256) void split_kernel(
    const float* __restrict__ in, __nv_bfloat16* __restrict__ hi,
    __nv_bfloat16* __restrict__ lo)
{
    size_t i = (size_t)blockIdx.x * 256 + threadIdx.x;
    float4 v = ((const float4*)in)[i];
    __nv_bfloat16 hx = __float2bfloat16(v.x);
    __nv_bfloat16 hy = __float2bfloat16(v.y);
    __nv_bfloat16 hz = __float2bfloat16(v.z);
    __nv_bfloat16 hw = __float2bfloat16(v.w);
    __nv_bfloat16 lx = __float2bfloat16(v.x - __bfloat162float(hx));
    __nv_bfloat16 ly = __float2bfloat16(v.y - __bfloat162float(hy));
    __nv_bfloat16 lz = __float2bfloat16(v.z - __bfloat162float(hz));
    __nv_bfloat16 lw = __float2bfloat16(v.w - __bfloat162float(hw));
    __nv_bfloat162* h2 = (__nv_bfloat162*)(hi + i * 4);
    __nv_bfloat162* l2 = (__nv_bfloat162*)(lo + i * 4);
    h2[0] = __nv_bfloat162(hx, hy); h2[1] = __nv_bfloat162(hz, hw);
    l2[0] = __nv_bfloat162(lx, ly); l2[1] = __nv_bfloat162(lz, lw);
}

// ================= attention kernels (SIMT fp32, round 2) ====================
__global__ __launch_bounds__(256) void qk_kernel(
    const float* __restrict__ Q, const float* __restrict__ Kk,
    float* __restrict__ L, int causal)
{
    int tid = threadIdx.x;
    int tr = tid >> 4;
    int tc = tid & 15;
    int bh = blockIdx.z;
    int b = bh >> 3, h = bh & 7;
    int q0 = blockIdx.y * 64;
    int c0 = blockIdx.x * 64;

    float* lb = L + (size_t)bh * SS * SS;

    if (causal && c0 > q0 + 63) {
        float4 neg = make_float4(-1e9f, -1e9f, -1e9f, -1e9f);
#pragma unroll
        for (int i = 0; i < 4; i++) {
            int q = q0 + tr * 4 + i;
            *reinterpret_cast<float4*>(&lb[(size_t)q * SS + c0 + tc * 4]) = neg;
        }
        return;
    }

    __shared__ float sQ[64][65];
    __shared__ float sK[64][65];

    const float* qb = Q + (size_t)b * SS * DD + (size_t)h * DKK;
    const float* kb = Kk + (size_t)b * SS * DD + (size_t)h * DKK;

#pragma unroll
    for (int i = tid; i < 64 * 64; i += 256) {
        int m = i >> 6, d = i & 63;
        sQ[m][d] = qb[(size_t)(q0 + m) * DD + d];
        sK[m][d] = kb[(size_t)(c0 + m) * DD + d];
    }
    __syncthreads();

    float acc[4][4];
#pragma unroll
    for (int i = 0; i < 4; i++)
#pragma unroll
        for (int j = 0; j < 4; j++) acc[i][j] = 0.f;

#pragma unroll
    for (int d = 0; d < 64; d++) {
        float a[4], bvv[4];
#pragma unroll
        for (int i = 0; i < 4; i++) a[i] = sQ[tr * 4 + i][d];
#pragma unroll
        for (int j = 0; j < 4; j++) bvv[j] = sK[tc * 4 + j][d];
#pragma unroll
        for (int i = 0; i < 4; i++)
#pragma unroll
            for (int j = 0; j < 4; j++) acc[i][j] = fmaf(a[i], bvv[j], acc[i][j]);
    }

#pragma unroll
    for (int i = 0; i < 4; i++) {
        int q = q0 + tr * 4 + i;
        float v0 = acc[i][0] * 0.125f, v1 = acc[i][1] * 0.125f;
        float v2 = acc[i][2] * 0.125f, v3 = acc[i][3] * 0.125f;
        int k = c0 + tc * 4;
        if (causal) {
            if (k + 0 > q) v0 += -1e9f;
            if (k + 1 > q) v1 += -1e9f;
            if (k + 2 > q) v2 += -1e9f;
            if (k + 3 > q) v3 += -1e9f;
        }
        float4 o; o.x = v0; o.y = v1; o.z = v2; o.w = v3;
        *reinterpret_cast<float4*>(&lb[(size_t)q * SS + k]) = o;
    }
}

__global__ __launch_bounds__(256) void softmax_kernel(float* __restrict__ P)
{
    __shared__ float red[256];
    size_t row = blockIdx.x;
    float* p = P + row * (size_t)SS;
    int tid = threadIdx.x;

    float4 v0 = *reinterpret_cast<float4*>(&p[tid * 4]);
    float4 v1 = *reinterpret_cast<float4*>(&p[1024 + tid * 4]);

    float mx = fmaxf(fmaxf(fmaxf(v0.x, v0.y), fmaxf(v0.z, v0.w)),
                     fmaxf(fmaxf(v1.x, v1.y), fmaxf(v1.z, v1.w)));
    red[tid] = mx; __syncthreads();
    for (int s = 128; s > 0; s >>= 1) {
        if (tid < s) red[tid] = fmaxf(red[tid], red[tid + s]);
        __syncthreads();
    }
    mx = red[0]; __syncthreads();

    v0.x = __expf(v0.x - mx); v0.y = __expf(v0.y - mx);
    v0.z = __expf(v0.z - mx); v0.w = __expf(v0.w - mx);
    v1.x = __expf(v1.x - mx); v1.y = __expf(v1.y - mx);
    v1.z = __expf(v1.z - mx); v1.w = __expf(v1.w - mx);

    float sum = v0.x + v0.y + v0.z + v0.w + v1.x + v1.y + v1.z + v1.w;
    red[tid] = sum; __syncthreads();
    for (int s = 128; s > 0; s >>= 1) {
        if (tid < s) red[tid] += red[tid + s];
        __syncthreads();
    }
    float inv = 1.f / red[0];

    v0.x *= inv; v0.y *= inv; v0.z *= inv; v0.w *= inv;
    v1.x *= inv; v1.y *= inv; v1.z *= inv; v1.w *= inv;
    *reinterpret_cast<float4*>(&p[tid * 4]) = v0;
    *reinterpret_cast<float4*>(&p[1024 + tid * 4]) = v1;
}

__global__ __launch_bounds__(256) void pv_kernel(
    const float* __restrict__ P, const float* __restrict__ V,
    float* __restrict__ O)
{
    __shared__ float sP[16][128];
    __shared__ float sV[16][64];

    int tid = threadIdx.x;
    int tr = tid >> 4;
    int tc = tid & 15;
    int bh = blockIdx.z;
    int b = bh >> 3, h = bh & 7;
    int q0 = blockIdx.y * 128;

    const float* pb = P + (size_t)bh * SS * SS;
    const float* vb = V + (size_t)b * SS * DD + (size_t)h * DKK;
    float* ob = O + (size_t)b * SS * DD + (size_t)h * DKK;

    float acc[8][4];
#pragma unroll
    for (int i = 0; i < 8; i++)
#pragma unroll
        for (int j = 0; j < 4; j++) acc[i][j] = 0.f;

    for (int k0 = 0; k0 < SS; k0 += 16) {
#pragma unroll
        for (int t = 0; t < 2; t++) {
            int idx = tid + t * 256;
            int m = idx >> 2;
            int kq = (idx & 3) * 4;
            float4 av = *reinterpret_cast<const float4*>(
                &pb[(size_t)(q0 + m) * SS + k0 + kq]);
            sP[kq + 0][m] = av.x;
            sP[kq + 1][m] = av.y;
            sP[kq + 2][m] = av.z;
            sP[kq + 3][m] = av.w;
        }
        {
            int kk = tid >> 4;
            int nq = (tid & 15) * 4;
            *reinterpret_cast<float4*>(&sV[kk][nq]) =
                *reinterpret_cast<const float4*>(&vb[(size_t)(k0 + kk) * DD + nq]);
        }
        __syncthreads();

#pragma unroll
        for (int kk = 0; kk < 16; kk++) {
            float a[8], bvv[4];
            *reinterpret_cast<float4*>(&a[0]) = *reinterpret_cast<float4*>(&sP[kk][tr * 8]);
            *reinterpret_cast<float4*>(&a[4]) = *reinterpret_cast<float4*>(&sP[kk][tr * 8 + 4]);
            *reinterpret_cast<float4*>(&bvv[0]) = *reinterpret_cast<float4*>(&sV[kk][tc * 4]);
#pragma unroll
            for (int i = 0; i < 8; i++)
#pragma unroll
                for (int j = 0; j < 4; j++) acc[i][j] = fmaf(a[i], bvv[j], acc[i][j]);
        }
        __syncthreads();
    }

#pragma unroll
    for (int i = 0; i < 8; i++) {
        int q = q0 + tr * 8 + i;
        float4 o;
        o.x = acc[i][0]; o.y = acc[i][1]; o.z = acc[i][2]; o.w = acc[i][3];
        *reinterpret_cast<float4*>(&ob[(size_t)q * DD + tc * 4]) = o;
    }
}

__global__ __launch_bounds__(128) void add_ln_kernel(
    const float* __restrict__ a, const float* __restrict__ res,
    const float* __restrict__ g, const float* __restrict__ be,
    float* __restrict__ out)
{
    __shared__ float red[128];
    size_t row = blockIdx.x;
    int tid = threadIdx.x;

    float4 va = *reinterpret_cast<const float4*>(&a[row * DD + tid * 4]);
    float4 vr = *reinterpret_cast<const float4*>(&res[row * DD + tid * 4]);
    float4 v;
    v.x = va.x + vr.x; v.y = va.y + vr.y; v.z = va.z + vr.z; v.w = va.w + vr.w;

    float s = v.x + v.y + v.z + v.w;
    red[tid] = s; __syncthreads();
    for (int st = 64; st > 0; st >>= 1) {
        if (tid < st) red[tid] += red[tid + st];
        __syncthreads();
    }
    float mean = red[0] * (1.f / DD); __syncthreads();

    float dx = v.x - mean, dy = v.y - mean, dz = v.z - mean, dw = v.w - mean;
    float sq = dx * dx + dy * dy + dz * dz + dw * dw;
    red[tid] = sq; __syncthreads();
    for (int st = 64; st > 0; st >>= 1) {
        if (tid < st) red[tid] += red[tid + st];
        __syncthreads();
    }
    float inv = rsqrtf(red[0] * (1.f / DD) + EPSV);

    float4 gg = *reinterpret_cast<const float4*>(&g[tid * 4]);
    float4 bb = *reinterpret_cast<const float4*>(&be[tid * 4]);
    float4 o;
    o.x = dx * inv * gg.x + bb.x;
    o.y = dy * inv * gg.y + bb.y;
    o.z = dz * inv * gg.z + bb.z;
    o.w = dw * inv * gg.w + bb.w;
    *reinterpret_cast<float4*>(&out[row * DD + tid * 4]) = o;
}

// ================= host side =================
extern "C" void kernel_launch(void* const* d_in, const int* in_sizes, int n_in,
                              void* d_out, int out_size)
{
    const float* x    = (const float*)d_in[0];
    const float* enc  = (const float*)d_in[1];
    const float* wq1 = (const float*)d_in[3];  const float* bq1 = (const float*)d_in[4];
    const float* wk1 = (const float*)d_in[5];  const float* bk1 = (const float*)d_in[6];
    const float* wv1 = (const float*)d_in[7];  const float* bv1 = (const float*)d_in[8];
    const float* wo1 = (const float*)d_in[9];  const float* bo1 = (const float*)d_in[10];
    const float* wq2 = (const float*)d_in[11]; const float* bq2 = (const float*)d_in[12];
    const float* wk2 = (const float*)d_in[13]; const float* bk2 = (const float*)d_in[14];
    const float* wv2 = (const float*)d_in[15]; const float* bv2 = (const float*)d_in[16];
    const float* wo2 = (const float*)d_in[17]; const float* bo2 = (const float*)d_in[18];
    const float* wf1 = (const float*)d_in[19]; const float* bf1 = (const float*)d_in[20];
    const float* wf2 = (const float*)d_in[21]; const float* bf2 = (const float*)d_in[22];
    const float* g1  = (const float*)d_in[23]; const float* be1 = (const float*)d_in[24];
    const float* g2  = (const float*)d_in[25]; const float* be2 = (const float*)d_in[26];
    const float* g3  = (const float*)d_in[27]; const float* be3 = (const float*)d_in[28];

    float* out3 = (float*)d_out;

    float *q, *k, *v, *tmp, *o1, *o2, *ffn, *attn;
    cudaGetSymbolAddress((void**)&q,    g_q);
    cudaGetSymbolAddress((void**)&k,    g_k);
    cudaGetSymbolAddress((void**)&v,    g_v);
    cudaGetSymbolAddress((void**)&tmp,  g_tmp);
    cudaGetSymbolAddress((void**)&o1,   g_out1);
    cudaGetSymbolAddress((void**)&o2,   g_out2);
    cudaGetSymbolAddress((void**)&ffn,  g_ffn);
    cudaGetSymbolAddress((void**)&attn, g_attn);
    __nv_bfloat16 *ah, *al, *bh, *bl, *wh, *wl;
    cudaGetSymbolAddress((void**)&ah, g_ah);
    cudaGetSymbolAddress((void**)&al, g_al);
    cudaGetSymbolAddress((void**)&bh, g_bh);
    cudaGetSymbolAddress((void**)&bl, g_bl);
    cudaGetSymbolAddress((void**)&wh, g_wh);
    cudaGetSymbolAddress((void**)&wl, g_wl);

    cudaFuncSetAttribute(mma_gemm_kernel,
                         cudaFuncAttributeMaxDynamicSharedMemorySize, SM_TOTAL);

    const size_t OUT3 = (size_t)BB * SS * DD;
    const size_t AW   = (size_t)BB * HH * SS * SS;
    float *p1, *p2;
    if ((size_t)out_size >= OUT3 + 2 * AW) {
        p1 = out3 + OUT3;
        p2 = out3 + OUT3 + AW;
    } else {
        p1 = attn;
        p2 = attn;
    }

    dim3 qkGrid(SS / 64, SS / 64, BB * HH);
    dim3 pvGrid(1, SS / 128, BB * HH);
    int nRows = BB * HH * SS;
    int nLn   = BB * SS;

    auto split = [&](const float* in, __nv_bfloat16* h, __nv_bfloat16* l, size_t n) {
        split_kernel<<<(unsigned)(n / 1024), 256>>>(in, h, l);
    };
    auto mgemm = [&](__nv_bfloat16* xh, __nv_bfloat16* xl, const float* bias,
                     float* C, int M, int N, int K, int relu) {
        mma_gemm_kernel<<<dim3(N / 128, M / 128), 256, SM_TOTAL>>>(
            xh, xl, wh, wl, bias, C, M, N, K, relu);
    };
    auto splitW = [&](const float* w, size_t n) { split(w, wh, wl, n); };

    // ================= MHA1 (causal self-attention) =================
    split(x, ah, al, (size_t)MM * DD);
    splitW(wq1, (size_t)DD * DD); mgemm(ah, al, bq1, q, MM, DD, DD, 0);
    splitW(wk1, (size_t)DD * DD); mgemm(ah, al, bk1, k, MM, DD, DD, 0);
    splitW(wv1, (size_t)DD * DD); mgemm(ah, al, bv1, v, MM, DD, DD, 0);
    qk_kernel<<<qkGrid, 256>>>(q, k, p1, 1);
    softmax_kernel<<<nRows, 256>>>(p1);
    pv_kernel<<<pvGrid, 256>>>(p1, v, tmp);
    split(tmp, ah, al, (size_t)MM * DD);
    splitW(wo1, (size_t)DD * DD); mgemm(ah, al, bo1, q, MM, DD, DD, 0);
    add_ln_kernel<<<nLn, 128>>>(q, x, g1, be1, o1);

    // ================= MHA2 (cross-attention) =======================
    split(o1, ah, al, (size_t)MM * DD);
    split(enc, bh, bl, (size_t)MM * DD);
    splitW(wq2, (size_t)DD * DD); mgemm(ah, al, bq2, q, MM, DD, DD, 0);
    splitW(wk2, (size_t)DD * DD); mgemm(bh, bl, bk2, k, MM, DD, DD, 0);
    splitW(wv2, (size_t)DD * DD); mgemm(bh, bl, bv2, v, MM, DD, DD, 0);
    qk_kernel<<<qkGrid, 256>>>(q, k, p2, 0);
    softmax_kernel<<<nRows, 256>>>(p2);
    pv_kernel<<<pvGrid, 256>>>(p2, v, tmp);
    split(tmp, ah, al, (size_t)MM * DD);
    splitW(wo2, (size_t)DD * DD); mgemm(ah, al, bo2, q, MM, DD, DD, 0);
    add_ln_kernel<<<nLn, 128>>>(q, o1, g2, be2, o2);

    // ================= FFN =================
    split(o2, ah, al, (size_t)MM * DD);
    splitW(wf1, (size_t)DD * FFN); mgemm(ah, al, bf1, ffn, MM, FFN, DD, 1);
    split(ffn, ah, al, (size_t)MM * FFN);
    splitW(wf2, (size_t)FFN * DD); mgemm(ah, al, bf2, q, MM, DD, FFN, 0);
    add_ln_kernel<<<nLn, 128>>>(q, o2, g3, be3, out3);
}

// round 6
// speedup vs baseline: 5.5797x; 1.8368x over previous
#include <cuda_runtime.h>
#include <cuda_bf16.h>
#include <math.h>
#include <stdint.h>

#define BB 2
#define SS 2048
#define DD 512
#define HH 8
#define DKK 64
#define FFN 2048
#define MM (BB*SS)
#define EPSV 1e-6f

// ================= scratch (device globals; allocation-free) ================
__device__ float g_attn[(size_t)BB*HH*SS*SS];   // logits scratch (no-aw case)
__device__ float g_qf  [MM*DD];                  // fp32 gemm out scratch
__device__ float g_out1[MM*DD];
__device__ float g_out2[MM*DD];
// bf16 planes
__device__ __nv_bfloat16 g_s1h[(size_t)MM*DD], g_s1l[(size_t)MM*DD];
__device__ __nv_bfloat16 g_s2h[(size_t)MM*DD], g_s2l[(size_t)MM*DD];
__device__ __nv_bfloat16 g_qh [(size_t)MM*DD], g_ql [(size_t)MM*DD];
__device__ __nv_bfloat16 g_kh [(size_t)MM*DD], g_kl [(size_t)MM*DD];
__device__ __nv_bfloat16 g_vh [(size_t)MM*DD];
__device__ __nv_bfloat16 g_th [(size_t)MM*DD], g_tl [(size_t)MM*DD];
__device__ __nv_bfloat16 g_ffh[(size_t)MM*FFN], g_ffl[(size_t)MM*FFN];
__device__ __nv_bfloat16 g_wh [(size_t)FFN*DD], g_wl [(size_t)FFN*DD];
__device__ __nv_bfloat16 g_ph [(size_t)BB*HH*SS*SS];   // probs bf16

// ================= low-level helpers (sm_80-compatible PTX only) ============
__device__ __forceinline__ uint32_t smem_u32(const void* p) {
    uint32_t a;
    asm("{ .reg .u64 t; cvta.to.shared.u64 t, %1; cvt.u32.u64 %0, t; }" : "=r"(a) : "l"(p));
    return a;
}
__device__ __forceinline__ void cp16(uint32_t dst, const void* src) {
    asm volatile("cp.async.cg.shared.global [%0], [%1], 16;" :: "r"(dst), "l"(src));
}
#define CP_COMMIT() asm volatile("cp.async.commit_group;" ::: "memory")
#define CP_WAIT1()  asm volatile("cp.async.wait_group 1;" ::: "memory")
#define CP_WAIT0()  asm volatile("cp.async.wait_group 0;" ::: "memory")

__device__ __forceinline__ void ldsm4(uint32_t& r0, uint32_t& r1, uint32_t& r2,
                                      uint32_t& r3, uint32_t addr) {
    asm volatile("ldmatrix.sync.aligned.m8n8.x4.shared.b16 {%0,%1,%2,%3}, [%4];"
                 : "=r"(r0), "=r"(r1), "=r"(r2), "=r"(r3) : "r"(addr));
}
__device__ __forceinline__ void ldsm4t(uint32_t& r0, uint32_t& r1, uint32_t& r2,
                                       uint32_t& r3, uint32_t addr) {
    asm volatile("ldmatrix.sync.aligned.m8n8.x4.trans.shared.b16 {%0,%1,%2,%3}, [%4];"
                 : "=r"(r0), "=r"(r1), "=r"(r2), "=r"(r3) : "r"(addr));
}
__device__ __forceinline__ void mma16816(float* c, const uint32_t* a, const uint32_t* b) {
    asm volatile(
        "mma.sync.aligned.m16n8k16.row.col.f32.bf16.bf16.f32 "
        "{%0,%1,%2,%3}, {%4,%5,%6,%7}, {%8,%9}, {%0,%1,%2,%3};"
        : "+f"(c[0]), "+f"(c[1]), "+f"(c[2]), "+f"(c[3])
        : "r"(a[0]), "r"(a[1]), "r"(a[2]), "r"(a[3]), "r"(b[0]), "r"(b[1]));
}
__device__ __forceinline__ uint32_t swz(uint32_t off) {
    return off ^ ((off >> 3) & 0x70);
}
__device__ __forceinline__ void split_bf16(float v, __nv_bfloat16& h, __nv_bfloat16& l) {
    h = __float2bfloat16(v);
    l = __float2bfloat16(v - __bfloat162float(h));
}

// ============== HMMA GEMM: C = A[M,K] @ W[K,N] + bias (bf16x3, fp32 acc) ====
// Optional outputs: fp32 C and/or split bf16 planes Ch/Cl.
#define STAGE_BYTES 65536
#define SM_TOTAL    (2*STAGE_BYTES)

__global__ __launch_bounds__(256) void mma_gemm_kernel(
    const __nv_bfloat16* __restrict__ Ah, const __nv_bfloat16* __restrict__ Al,
    const __nv_bfloat16* __restrict__ Bh, const __nv_bfloat16* __restrict__ Bl,
    const float* __restrict__ bias, float* __restrict__ C,
    __nv_bfloat16* __restrict__ Ch, __nv_bfloat16* __restrict__ Cl,
    int M, int N, int K, int relu)
{
    extern __shared__ char smem[];
    const int tid = threadIdx.x;
    const int lane = tid & 31;
    const int wid = tid >> 5;
    const int warp_m = wid & 1;
    const int warp_n = wid >> 1;
    const int rowBase = blockIdx.y * 128;
    const int colBase = blockIdx.x * 128;
    const uint32_t sbase = smem_u32(smem);

    float acc[4][4][4];
#pragma unroll
    for (int i = 0; i < 4; i++)
#pragma unroll
        for (int j = 0; j < 4; j++)
#pragma unroll
            for (int t = 0; t < 4; t++) acc[i][j][t] = 0.f;

    const int nChunks = K >> 6;

    auto load_stage = [&](int kc, int s) {
        uint32_t st = sbase + s * STAGE_BYTES;
        int k0 = kc * 64;
#pragma unroll
        for (int i = 0; i < 4; i++) {
            int id = tid + i * 256;
            int r = id >> 3, c16 = id & 7;
            uint32_t off = swz((uint32_t)(r * 128 + c16 * 16));
            size_t g = (size_t)(rowBase + r) * K + k0 + c16 * 8;
            cp16(st + off,         Ah + g);
            cp16(st + 16384 + off, Al + g);
        }
#pragma unroll
        for (int i = 0; i < 4; i++) {
            int id = tid + i * 256;
            int kk = id >> 4, nc = id & 15;
            int j = nc >> 3, cc = nc & 7;
            uint32_t off = swz((uint32_t)(kk * 128 + cc * 16)) + (uint32_t)(j * 8192);
            size_t g = (size_t)(k0 + kk) * N + colBase + nc * 8;
            cp16(st + 32768 + off, Bh + g);
            cp16(st + 49152 + off, Bl + g);
        }
    };

    load_stage(0, 0);
    CP_COMMIT();

    const int bsub = warp_n >> 1;
    const int nb2  = (warp_n & 1) * 64;

    for (int c = 0; c < nChunks; c++) {
        if (c + 1 < nChunks) load_stage(c + 1, (c + 1) & 1);
        CP_COMMIT();
        CP_WAIT1();
        __syncthreads();

        uint32_t st = sbase + (c & 1) * STAGE_BYTES;
#pragma unroll
        for (int k16 = 0; k16 < 4; k16++) {
            uint32_t ahf[4][4], alf[4][4], bhf[2][4], blf[2][4];
#pragma unroll
            for (int mt = 0; mt < 4; mt++) {
                int row = warp_m * 64 + mt * 16 + (lane & 15);
                uint32_t off = swz((uint32_t)(row * 128 + k16 * 32 + (lane >> 4) * 16));
                ldsm4(ahf[mt][0], ahf[mt][1], ahf[mt][2], ahf[mt][3], st + off);
                ldsm4(alf[mt][0], alf[mt][1], alf[mt][2], alf[mt][3], st + 16384 + off);
            }
#pragma unroll
            for (int nt = 0; nt < 2; nt++) {
                int kk = k16 * 16 + (lane & 15);
                uint32_t off = swz((uint32_t)(kk * 128 + nb2 + nt * 32 + (lane >> 4) * 16))
                             + (uint32_t)(bsub * 8192);
                ldsm4t(bhf[nt][0], bhf[nt][1], bhf[nt][2], bhf[nt][3], st + 32768 + off);
                ldsm4t(blf[nt][0], blf[nt][1], blf[nt][2], blf[nt][3], st + 49152 + off);
            }
#pragma unroll
            for (int mt = 0; mt < 4; mt++) {
#pragma unroll
                for (int n8 = 0; n8 < 4; n8++) {
                    const uint32_t* bh = &bhf[n8 >> 1][(n8 & 1) * 2];
                    const uint32_t* bl = &blf[n8 >> 1][(n8 & 1) * 2];
                    mma16816(acc[mt][n8], ahf[mt], bh);
                    mma16816(acc[mt][n8], alf[mt], bh);
                    mma16816(acc[mt][n8], ahf[mt], bl);
                }
            }
        }
        __syncthreads();
    }

#pragma unroll
    for (int mt = 0; mt < 4; mt++) {
        int r0 = rowBase + warp_m * 64 + mt * 16 + (lane >> 2);
#pragma unroll
        for (int n8 = 0; n8 < 4; n8++) {
            int col = colBase + warp_n * 32 + n8 * 8 + (lane & 3) * 2;
            float bx = bias[col], by = bias[col + 1];
            float v00 = acc[mt][n8][0] + bx, v01 = acc[mt][n8][1] + by;
            float v10 = acc[mt][n8][2] + bx, v11 = acc[mt][n8][3] + by;
            if (relu) {
                v00 = fmaxf(v00, 0.f); v01 = fmaxf(v01, 0.f);
                v10 = fmaxf(v10, 0.f); v11 = fmaxf(v11, 0.f);
            }
            if (C) {
                *(float2*)&C[(size_t)r0 * N + col] = make_float2(v00, v01);
                *(float2*)&C[(size_t)(r0 + 8) * N + col] = make_float2(v10, v11);
            }
            if (Ch) {
                __nv_bfloat16 h00, l00, h01, l01, h10, l10, h11, l11;
                split_bf16(v00, h00, l00); split_bf16(v01, h01, l01);
                split_bf16(v10, h10, l10); split_bf16(v11, h11, l11);
                *(__nv_bfloat162*)&Ch[(size_t)r0 * N + col] = __nv_bfloat162(h00, h01);
                *(__nv_bfloat162*)&Ch[(size_t)(r0 + 8) * N + col] = __nv_bfloat162(h10, h11);
                if (Cl) {
                    *(__nv_bfloat162*)&Cl[(size_t)r0 * N + col] = __nv_bfloat162(l00, l01);
                    *(__nv_bfloat162*)&Cl[(size_t)(r0 + 8) * N + col] = __nv_bfloat162(l10, l11);
                }
            }
        }
    }
}

// ================= fp32 -> (hi, lo) bf16 split, elementwise =================
__global__ __launch_bounds__(256) void split_kernel(
    const float* __restrict__ in, __nv_bfloat16* __restrict__ hi,
    __nv_bfloat16* __restrict__ lo)
{
    size_t i = (size_t)blockIdx.x * 256 + threadIdx.x;
    float4 v = ((const float4*)in)[i];
    __nv_bfloat16 hx, lx, hy, ly, hz, lz, hw, lw;
    split_bf16(v.x, hx, lx); split_bf16(v.y, hy, ly);
    split_bf16(v.z, hz, lz); split_bf16(v.w, hw, lw);
    __nv_bfloat162* h2 = (__nv_bfloat162*)(hi + i * 4);
    __nv_bfloat162* l2 = (__nv_bfloat162*)(lo + i * 4);
    h2[0] = __nv_bfloat162(hx, hy); h2[1] = __nv_bfloat162(hz, hw);
    l2[0] = __nv_bfloat162(lx, ly); l2[1] = __nv_bfloat162(lz, lw);
}

// ================= QK^T via HMMA (bf16x3), fused scale, causal skip =========
// Q,K planes: [B,S,D] row-major with head cols h*64. Tile 128q x 128k, K=64.
#define QK_SM 65536
__global__ __launch_bounds__(256) void qk_mma_kernel(
    const __nv_bfloat16* __restrict__ Qh, const __nv_bfloat16* __restrict__ Ql,
    const __nv_bfloat16* __restrict__ Kh, const __nv_bfloat16* __restrict__ Kl,
    float* __restrict__ L, int causal)
{
    const int q0 = blockIdx.y * 128;
    const int c0 = blockIdx.x * 128;
    if (causal && c0 > q0 + 127) return;   // fully masked: softmax never reads it

    extern __shared__ char smem[];
    const int tid = threadIdx.x;
    const int lane = tid & 31;
    const int wid = tid >> 5;
    const int warp_m = wid & 1;
    const int warp_n = wid >> 1;
    const int bh = blockIdx.z;
    const int b = bh >> 3, h = bh & 7;
    const uint32_t sbase = smem_u32(smem);

    const __nv_bfloat16* qhp = Qh + (size_t)b * SS * DD + (size_t)h * DKK;
    const __nv_bfloat16* qlp = Ql + (size_t)b * SS * DD + (size_t)h * DKK;
    const __nv_bfloat16* khp = Kh + (size_t)b * SS * DD + (size_t)h * DKK;
    const __nv_bfloat16* klp = Kl + (size_t)b * SS * DD + (size_t)h * DKK;

    // load 4 planes of 128 rows x 64 bf16 (16KB each)
#pragma unroll
    for (int i = 0; i < 4; i++) {
        int id = tid + i * 256;
        int r = id >> 3, c16 = id & 7;
        uint32_t off = swz((uint32_t)(r * 128 + c16 * 16));
        size_t gq = (size_t)(q0 + r) * DD + c16 * 8;
        size_t gk = (size_t)(c0 + r) * DD + c16 * 8;
        cp16(sbase + off,         qhp + gq);
        cp16(sbase + 16384 + off, qlp + gq);
        cp16(sbase + 32768 + off, khp + gk);
        cp16(sbase + 49152 + off, klp + gk);
    }
    CP_COMMIT();
    CP_WAIT0();
    __syncthreads();

    float acc[4][4][4];
#pragma unroll
    for (int i = 0; i < 4; i++)
#pragma unroll
        for (int j = 0; j < 4; j++)
#pragma unroll
            for (int t = 0; t < 4; t++) acc[i][j][t] = 0.f;

#pragma unroll
    for (int k16 = 0; k16 < 4; k16++) {
        uint32_t ahf[4][4], alf[4][4], bhf[2][4], blf[2][4];
#pragma unroll
        for (int mt = 0; mt < 4; mt++) {
            int row = warp_m * 64 + mt * 16 + (lane & 15);
            uint32_t off = swz((uint32_t)(row * 128 + k16 * 32 + (lane >> 4) * 16));
            ldsm4(ahf[mt][0], ahf[mt][1], ahf[mt][2], ahf[mt][3], sbase + off);
            ldsm4(alf[mt][0], alf[mt][1], alf[mt][2], alf[mt][3], sbase + 16384 + off);
        }
        // B operand: non-trans ldmatrix on K rows (K row-major == B col-major)
#pragma unroll
        for (int nt = 0; nt < 2; nt++) {
            int tok = warp_n * 32 + nt * 16 + (lane >> 4) * 8 + (lane & 7);
            uint32_t off = swz((uint32_t)(tok * 128 + k16 * 32 + ((lane >> 3) & 1) * 16));
            ldsm4(bhf[nt][0], bhf[nt][1], bhf[nt][2], bhf[nt][3], sbase + 32768 + off);
            ldsm4(blf[nt][0], blf[nt][1], blf[nt][2], blf[nt][3], sbase + 49152 + off);
        }
#pragma unroll
        for (int mt = 0; mt < 4; mt++) {
#pragma unroll
            for (int n8 = 0; n8 < 4; n8++) {
                const uint32_t* bh2 = &bhf[n8 >> 1][(n8 & 1) * 2];
                const uint32_t* bl2 = &blf[n8 >> 1][(n8 & 1) * 2];
                mma16816(acc[mt][n8], ahf[mt], bh2);
                mma16816(acc[mt][n8], alf[mt], bh2);
                mma16816(acc[mt][n8], ahf[mt], bl2);
            }
        }
    }

    float* lb = L + (size_t)bh * SS * SS;
#pragma unroll
    for (int mt = 0; mt < 4; mt++) {
        int q = q0 + warp_m * 64 + mt * 16 + (lane >> 2);
#pragma unroll
        for (int n8 = 0; n8 < 4; n8++) {
            int kc = c0 + warp_n * 32 + n8 * 8 + (lane & 3) * 2;
            *(float2*)&lb[(size_t)q * SS + kc] =
                make_float2(acc[mt][n8][0] * 0.125f, acc[mt][n8][1] * 0.125f);
            *(float2*)&lb[(size_t)(q + 8) * SS + kc] =
                make_float2(acc[mt][n8][2] * 0.125f, acc[mt][n8][3] * 0.125f);
        }
    }
}

// ============== softmax: fp32 logits -> bf16 probs (+ optional fp32) ========
__global__ __launch_bounds__(256) void softmax_kernel(
    float* __restrict__ L, __nv_bfloat16* __restrict__ Ph,
    int causal, int writeF32)
{
    __shared__ float red[256];
    size_t row = blockIdx.x;
    int q = (int)(row & (SS - 1));
    float* p = L + row * (size_t)SS;
    __nv_bfloat16* ph = Ph + row * (size_t)SS;
    int tid = threadIdx.x;
    int valid = causal ? q + 1 : SS;

    int c0 = tid * 4, c1 = 1024 + tid * 4;
    float4 v0 = make_float4(-INFINITY, -INFINITY, -INFINITY, -INFINITY);
    float4 v1 = v0;
    if (c0 < valid) v0 = *reinterpret_cast<float4*>(&p[c0]);
    if (c1 < valid) v1 = *reinterpret_cast<float4*>(&p[c1]);
    if (c0 + 1 >= valid) v0.y = -INFINITY;
    if (c0 + 2 >= valid) v0.z = -INFINITY;
    if (c0 + 3 >= valid) v0.w = -INFINITY;
    if (c1 + 1 >= valid) v1.y = -INFINITY;
    if (c1 + 2 >= valid) v1.z = -INFINITY;
    if (c1 + 3 >= valid) v1.w = -INFINITY;

    float mx = fmaxf(fmaxf(fmaxf(v0.x, v0.y), fmaxf(v0.z, v0.w)),
                     fmaxf(fmaxf(v1.x, v1.y), fmaxf(v1.z, v1.w)));
    red[tid] = mx; __syncthreads();
    for (int s = 128; s > 0; s >>= 1) {
        if (tid < s) red[tid] = fmaxf(red[tid], red[tid + s]);
        __syncthreads();
    }
    mx = red[0]; __syncthreads();

    float e[8];
    e[0] = (c0 + 0 < valid) ? __expf(v0.x - mx) : 0.f;
    e[1] = (c0 + 1 < valid) ? __expf(v0.y - mx) : 0.f;
    e[2] = (c0 + 2 < valid) ? __expf(v0.z - mx) : 0.f;
    e[3] = (c0 + 3 < valid) ? __expf(v0.w - mx) : 0.f;
    e[4] = (c1 + 0 < valid) ? __expf(v1.x - mx) : 0.f;
    e[5] = (c1 + 1 < valid) ? __expf(v1.y - mx) : 0.f;
    e[6] = (c1 + 2 < valid) ? __expf(v1.z - mx) : 0.f;
    e[7] = (c1 + 3 < valid) ? __expf(v1.w - mx) : 0.f;

    float sum = e[0] + e[1] + e[2] + e[3] + e[4] + e[5] + e[6] + e[7];
    red[tid] = sum; __syncthreads();
    for (int s = 128; s > 0; s >>= 1) {
        if (tid < s) red[tid] += red[tid + s];
        __syncthreads();
    }
    float inv = 1.f / red[0];
#pragma unroll
    for (int i = 0; i < 8; i++) e[i] *= inv;

    // bf16 probs (8 bf16 = two 8B chunks)
    __nv_bfloat162 b0 = __floats2bfloat162_rn(e[0], e[1]);
    __nv_bfloat162 b1 = __floats2bfloat162_rn(e[2], e[3]);
    __nv_bfloat162 b2 = __floats2bfloat162_rn(e[4], e[5]);
    __nv_bfloat162 b3 = __floats2bfloat162_rn(e[6], e[7]);
    *(__nv_bfloat162*)&ph[c0]     = b0;
    *(__nv_bfloat162*)&ph[c0 + 2] = b1;
    *(__nv_bfloat162*)&ph[c1]     = b2;
    *(__nv_bfloat162*)&ph[c1 + 2] = b3;

    if (writeF32) {
        *reinterpret_cast<float4*>(&p[c0]) = make_float4(e[0], e[1], e[2], e[3]);
        *reinterpret_cast<float4*>(&p[c1]) = make_float4(e[4], e[5], e[6], e[7]);
    }
}

// ================= PV via HMMA: O = P(bf16) @ V(bf16) -> split bf16 =========
// Tile 128q x 64n, K-chunk 64, 2-stage. grid (qblk=16, bh=16).
#define PV_STAGE 24576
#define PV_SM (2*PV_STAGE)
__global__ __launch_bounds__(256) void pv_mma_kernel(
    const __nv_bfloat16* __restrict__ P, const __nv_bfloat16* __restrict__ Vh,
    __nv_bfloat16* __restrict__ Th, __nv_bfloat16* __restrict__ Tl,
    int causal)
{
    extern __shared__ char smem[];
    const int tid = threadIdx.x;
    const int lane = tid & 31;
    const int wid = tid >> 5;
    const int warp_m = wid >> 1;   // 0..3 (32 rows)
    const int warp_n = wid & 1;    // 0..1 (32 cols)
    const int q0 = blockIdx.x * 128;
    const int bh = blockIdx.y;
    const int b = bh >> 3, h = bh & 7;
    const uint32_t sbase = smem_u32(smem);

    const __nv_bfloat16* pb = P + (size_t)bh * SS * SS;
    const __nv_bfloat16* vb = Vh + (size_t)b * SS * DD + (size_t)h * DKK;

    float acc[2][4][4];
#pragma unroll
    for (int i = 0; i < 2; i++)
#pragma unroll
        for (int j = 0; j < 4; j++)
#pragma unroll
            for (int t = 0; t < 4; t++) acc[i][j][t] = 0.f;

    const int nCh = causal ? (q0 >> 6) + 2 : (SS >> 6);

    auto load_stage = [&](int kc, int s) {
        uint32_t st = sbase + s * PV_STAGE;
        int k0 = kc * 64;
#pragma unroll
        for (int i = 0; i < 4; i++) {
            int id = tid + i * 256;
            int r = id >> 3, c16 = id & 7;
            uint32_t off = swz((uint32_t)(r * 128 + c16 * 16));
            cp16(st + off, pb + (size_t)(q0 + r) * SS + k0 + c16 * 8);
        }
#pragma unroll
        for (int i = 0; i < 2; i++) {
            int id = tid + i * 256;
            int kk = id >> 3, c16 = id & 7;
            uint32_t off = swz((uint32_t)(kk * 128 + c16 * 16));
            cp16(st + 16384 + off, vb + (size_t)(k0 + kk) * DD + c16 * 8);
        }
    };

    load_stage(0, 0);
    CP_COMMIT();

    for (int c = 0; c < nCh; c++) {
        if (c + 1 < nCh) load_stage(c + 1, (c + 1) & 1);
        CP_COMMIT();
        CP_WAIT1();
        __syncthreads();

        uint32_t st = sbase + (c & 1) * PV_STAGE;
#pragma unroll
        for (int k16 = 0; k16 < 4; k16++) {
            uint32_t pf[2][4], vf[2][4];
#pragma unroll
            for (int mt = 0; mt < 2; mt++) {
                int row = warp_m * 32 + mt * 16 + (lane & 15);
                uint32_t off = swz((uint32_t)(row * 128 + k16 * 32 + (lane >> 4) * 16));
                ldsm4(pf[mt][0], pf[mt][1], pf[mt][2], pf[mt][3], st + off);
            }
#pragma unroll
            for (int nt = 0; nt < 2; nt++) {
                int kk = k16 * 16 + (lane & 15);
                uint32_t off = swz((uint32_t)(kk * 128 + warp_n * 64 + nt * 32 + (lane >> 4) * 16));
                ldsm4t(vf[nt][0], vf[nt][1], vf[nt][2], vf[nt][3], st + 16384 + off);
            }
#pragma unroll
            for (int mt = 0; mt < 2; mt++)
#pragma unroll
                for (int n8 = 0; n8 < 4; n8++)
                    mma16816(acc[mt][n8], pf[mt], &vf[n8 >> 1][(n8 & 1) * 2]);
        }
        __syncthreads();
    }

#pragma unroll
    for (int mt = 0; mt < 2; mt++) {
        int r0 = q0 + warp_m * 32 + mt * 16 + (lane >> 2);
#pragma unroll
        for (int n8 = 0; n8 < 4; n8++) {
            int gcol = h * 64 + warp_n * 32 + n8 * 8 + (lane & 3) * 2;
            size_t o0 = (size_t)(b * SS + r0) * DD + gcol;
            size_t o1 = (size_t)(b * SS + r0 + 8) * DD + gcol;
            __nv_bfloat16 h00, l00, h01, l01, h10, l10, h11, l11;
            split_bf16(acc[mt][n8][0], h00, l00);
            split_bf16(acc[mt][n8][1], h01, l01);
            split_bf16(acc[mt][n8][2], h10, l10);
            split_bf16(acc[mt][n8][3], h11, l11);
            *(__nv_bfloat162*)&Th[o0] = __nv_bfloat162(h00, h01);
            *(__nv_bfloat162*)&Th[o1] = __nv_bfloat162(h10, h11);
            *(__nv_bfloat162*)&Tl[o0] = __nv_bfloat162(l00, l01);
            *(__nv_bfloat162*)&Tl[o1] = __nv_bfloat162(l10, l11);
        }
    }
}

// ========== residual add + LayerNorm (+ optional fused bf16 split out) ======
__global__ __launch_bounds__(128) void add_ln_kernel(
    const float* __restrict__ a, const float* __restrict__ res,
    const float* __restrict__ g, const float* __restrict__ be,
    float* __restrict__ out,
    __nv_bfloat16* __restrict__ Ch, __nv_bfloat16* __restrict__ Cl)
{
    __shared__ float red[128];
    size_t row = blockIdx.x;
    int tid = threadIdx.x;

    float4 va = *reinterpret_cast<const float4*>(&a[row * DD + tid * 4]);
    float4 vr = *reinterpret_cast<const float4*>(&res[row * DD + tid * 4]);
    float4 v;
    v.x = va.x + vr.x; v.y = va.y + vr.y; v.z = va.z + vr.z; v.w = va.w + vr.w;

    float s = v.x + v.y + v.z + v.w;
    red[tid] = s; __syncthreads();
    for (int st = 64; st > 0; st >>= 1) {
        if (tid < st) red[tid] += red[tid + st];
        __syncthreads();
    }
    float mean = red[0] * (1.f / DD); __syncthreads();

    float dx = v.x - mean, dy = v.y - mean, dz = v.z - mean, dw = v.w - mean;
    float sq = dx * dx + dy * dy + dz * dz + dw * dw;
    red[tid] = sq; __syncthreads();
    for (int st = 64; st > 0; st >>= 1) {
        if (tid < st) red[tid] += red[tid + st];
        __syncthreads();
    }
    float inv = rsqrtf(red[0] * (1.f / DD) + EPSV);

    float4 gg = *reinterpret_cast<const float4*>(&g[tid * 4]);
    float4 bb = *reinterpret_cast<const float4*>(&be[tid * 4]);
    float4 o;
    o.x = dx * inv * gg.x + bb.x;
    o.y = dy * inv * gg.y + bb.y;
    o.z = dz * inv * gg.z + bb.z;
    o.w = dw * inv * gg.w + bb.w;
    *reinterpret_cast<float4*>(&out[row * DD + tid * 4]) = o;

    if (Ch) {
        __nv_bfloat16 hx, lx, hy, ly, hz, lz, hw, lw;
        split_bf16(o.x, hx, lx); split_bf16(o.y, hy, ly);
        split_bf16(o.z, hz, lz); split_bf16(o.w, hw, lw);
        size_t idx = row * DD + tid * 4;
        *(__nv_bfloat162*)&Ch[idx]     = __nv_bfloat162(hx, hy);
        *(__nv_bfloat162*)&Ch[idx + 2] = __nv_bfloat162(hz, hw);
        *(__nv_bfloat162*)&Cl[idx]     = __nv_bfloat162(lx, ly);
        *(__nv_bfloat162*)&Cl[idx + 2] = __nv_bfloat162(lz, lw);
    }
}

// ================= host side =================
extern "C" void kernel_launch(void* const* d_in, const int* in_sizes, int n_in,
                              void* d_out, int out_size)
{
    const float* x    = (const float*)d_in[0];
    const float* enc  = (const float*)d_in[1];
    const float* wq1 = (const float*)d_in[3];  const float* bq1 = (const float*)d_in[4];
    const float* wk1 = (const float*)d_in[5];  const float* bk1 = (const float*)d_in[6];
    const float* wv1 = (const float*)d_in[7];  const float* bv1 = (const float*)d_in[8];
    const float* wo1 = (const float*)d_in[9];  const float* bo1 = (const float*)d_in[10];
    const float* wq2 = (const float*)d_in[11]; const float* bq2 = (const float*)d_in[12];
    const float* wk2 = (const float*)d_in[13]; const float* bk2 = (const float*)d_in[14];
    const float* wv2 = (const float*)d_in[15]; const float* bv2 = (const float*)d_in[16];
    const float* wo2 = (const float*)d_in[17]; const float* bo2 = (const float*)d_in[18];
    const float* wf1 = (const float*)d_in[19]; const float* bf1 = (const float*)d_in[20];
    const float* wf2 = (const float*)d_in[21]; const float* bf2 = (const float*)d_in[22];
    const float* g1  = (const float*)d_in[23]; const float* be1 = (const float*)d_in[24];
    const float* g2  = (const float*)d_in[25]; const float* be2 = (const float*)d_in[26];
    const float* g3  = (const float*)d_in[27]; const float* be3 = (const float*)d_in[28];

    float* out3 = (float*)d_out;

    float *attn, *qf, *o1, *o2;
    cudaGetSymbolAddress((void**)&attn, g_attn);
    cudaGetSymbolAddress((void**)&qf,   g_qf);
    cudaGetSymbolAddress((void**)&o1,   g_out1);
    cudaGetSymbolAddress((void**)&o2,   g_out2);
    __nv_bfloat16 *s1h, *s1l, *s2h, *s2l, *qh, *ql, *kh, *kl, *vh, *th, *tl;
    __nv_bfloat16 *ffh, *ffl, *wh, *wl, *ph;
    cudaGetSymbolAddress((void**)&s1h, g_s1h); cudaGetSymbolAddress((void**)&s1l, g_s1l);
    cudaGetSymbolAddress((void**)&s2h, g_s2h); cudaGetSymbolAddress((void**)&s2l, g_s2l);
    cudaGetSymbolAddress((void**)&qh,  g_qh);  cudaGetSymbolAddress((void**)&ql,  g_ql);
    cudaGetSymbolAddress((void**)&kh,  g_kh);  cudaGetSymbolAddress((void**)&kl,  g_kl);
    cudaGetSymbolAddress((void**)&vh,  g_vh);
    cudaGetSymbolAddress((void**)&th,  g_th);  cudaGetSymbolAddress((void**)&tl,  g_tl);
    cudaGetSymbolAddress((void**)&ffh, g_ffh); cudaGetSymbolAddress((void**)&ffl, g_ffl);
    cudaGetSymbolAddress((void**)&wh,  g_wh);  cudaGetSymbolAddress((void**)&wl,  g_wl);
    cudaGetSymbolAddress((void**)&ph,  g_ph);

    cudaFuncSetAttribute(mma_gemm_kernel, cudaFuncAttributeMaxDynamicSharedMemorySize, SM_TOTAL);
    cudaFuncSetAttribute(qk_mma_kernel,  cudaFuncAttributeMaxDynamicSharedMemorySize, QK_SM);
    cudaFuncSetAttribute(pv_mma_kernel,  cudaFuncAttributeMaxDynamicSharedMemorySize, PV_SM);

    const size_t OUT3 = (size_t)BB * SS * DD;
    const size_t AW   = (size_t)BB * HH * SS * SS;
    int awOut = ((size_t)out_size >= OUT3 + 2 * AW) ? 1 : 0;
    float* p1 = awOut ? out3 + OUT3       : attn;
    float* p2 = awOut ? out3 + OUT3 + AW  : attn;

    dim3 qkGrid(SS / 128, SS / 128, BB * HH);
    dim3 pvGrid(SS / 128, BB * HH);
    int nRows = BB * HH * SS;
    int nLn   = BB * SS;

    auto split = [&](const float* in, __nv_bfloat16* h, __nv_bfloat16* l, size_t n) {
        split_kernel<<<(unsigned)(n / 1024), 256>>>(in, h, l);
    };
    auto proj = [&](const __nv_bfloat16* xh, const __nv_bfloat16* xl,
                    const float* bias, float* C, __nv_bfloat16* Ch, __nv_bfloat16* Cl,
                    int M, int N, int K, int relu) {
        mma_gemm_kernel<<<dim3(N / 128, M / 128), 256, SM_TOTAL>>>(
            xh, xl, wh, wl, bias, C, Ch, Cl, M, N, K, relu);
    };

    // ================= MHA1 (causal self-attention) =================
    split(x, s1h, s1l, (size_t)MM * DD);
    split(wq1, wh, wl, (size_t)DD * DD); proj(s1h, s1l, bq1, 0, qh, ql, MM, DD, DD, 0);
    split(wk1, wh, wl, (size_t)DD * DD); proj(s1h, s1l, bk1, 0, kh, kl, MM, DD, DD, 0);
    split(wv1, wh, wl, (size_t)DD * DD); proj(s1h, s1l, bv1, 0, vh, 0,  MM, DD, DD, 0);
    qk_mma_kernel<<<qkGrid, 256, QK_SM>>>(qh, ql, kh, kl, p1, 1);
    softmax_kernel<<<nRows, 256>>>(p1, ph, 1, awOut);
    pv_mma_kernel<<<pvGrid, 256, PV_SM>>>(ph, vh, th, tl, 1);
    split(wo1, wh, wl, (size_t)DD * DD); proj(th, tl, bo1, qf, 0, 0, MM, DD, DD, 0);
    add_ln_kernel<<<nLn, 128>>>(qf, x, g1, be1, o1, s1h, s1l);

    // ================= MHA2 (cross-attention) =======================
    split(enc, s2h, s2l, (size_t)MM * DD);
    split(wq2, wh, wl, (size_t)DD * DD); proj(s1h, s1l, bq2, 0, qh, ql, MM, DD, DD, 0);
    split(wk2, wh, wl, (size_t)DD * DD); proj(s2h, s2l, bk2, 0, kh, kl, MM, DD, DD, 0);
    split(wv2, wh, wl, (size_t)DD * DD); proj(s2h, s2l, bv2, 0, vh, 0,  MM, DD, DD, 0);
    qk_mma_kernel<<<qkGrid, 256, QK_SM>>>(qh, ql, kh, kl, p2, 0);
    softmax_kernel<<<nRows, 256>>>(p2, ph, 0, awOut);
    pv_mma_kernel<<<pvGrid, 256, PV_SM>>>(ph, vh, th, tl, 0);
    split(wo2, wh, wl, (size_t)DD * DD); proj(th, tl, bo2, qf, 0, 0, MM, DD, DD, 0);
    add_ln_kernel<<<nLn, 128>>>(qf, o1, g2, be2, o2, s1h, s1l);

    // ================= FFN =================
    split(wf1, wh, wl, (size_t)DD * FFN); proj(s1h, s1l, bf1, 0, ffh, ffl, MM, FFN, DD, 1);
    split(wf2, wh, wl, (size_t)FFN * DD); proj(ffh, ffl, bf2, qf, 0, 0, MM, DD, FFN, 0);
    add_ln_kernel<<<nLn, 128>>>(qf, o2, g3, be3, out3, 0, 0);
}